// round 1
// baseline (speedup 1.0000x reference)
#include <cuda_runtime.h>

#define NPERSEG 1024
#define STEP     256
#define SEQ    16384
#define NWIN      61
#define BATCH   1024
#define THREADS  256

// Precomputed per-sample weights (fp32, float4-aligned). 2 * 64KB, lives in L2.
__device__ float4 g_wre4[SEQ / 4];
__device__ float4 g_wim4[SEQ / 4];

// Kernel 1: collapse the windowing + cos/sin projection + window-mean into a
// single per-sample weight pair. Each sample index s belongs to at most
// NPERSEG/STEP = 4 windows; p = (s mod 256) + 256k, w = (s - p)/256.
__global__ void build_weights_kernel(const float* __restrict__ freqs) {
    int s = blockIdx.x * blockDim.x + threadIdx.x;
    if (s >= SEQ) return;
    const float TWO_PI = 6.283185307179586476925f;
    float wre = 0.f, wim = 0.f;
    int pbase = s & (STEP - 1);
    #pragma unroll
    for (int k = 0; k < 4; ++k) {
        int p = pbase + k * STEP;
        int w = (s - p) >> 8;           // exact: s - p is a multiple of 256
        if (w >= 0 && w < NWIN) {
            float ang = TWO_PI * freqs[p];
            float sn, cs;
            sincosf(ang, &sn, &cs);     // precise variant; negligible cost here
            wre += cs;
            wim -= sn;
        }
    }
    const float inv = 1.0f / (float)NWIN;
    float* wre_f = (float*)g_wre4;
    float* wim_f = (float*)g_wim4;
    wre_f[s] = wre * inv;
    wim_f[s] = wim * inv;
}

// Kernel 2: one CTA per batch row. Two weighted reductions over 16384 fp32
// (float4 loads), block reduce, fused |.|^2 + affine epilogue.
__global__ __launch_bounds__(THREADS) void welch_reduce_kernel(
    const float4* __restrict__ in,
    const float*  __restrict__ fc_w,
    const float*  __restrict__ fc_b,
    float*        __restrict__ out)
{
    const int b = blockIdx.x;
    const float4* __restrict__ row = in + (size_t)b * (SEQ / 4);

    float re = 0.f, im = 0.f;
    #pragma unroll 4
    for (int i = threadIdx.x; i < SEQ / 4; i += THREADS) {
        float4 x  = row[i];
        float4 cr = g_wre4[i];
        float4 ci = g_wim4[i];
        re = fmaf(x.x, cr.x, re); re = fmaf(x.y, cr.y, re);
        re = fmaf(x.z, cr.z, re); re = fmaf(x.w, cr.w, re);
        im = fmaf(x.x, ci.x, im); im = fmaf(x.y, ci.y, im);
        im = fmaf(x.z, ci.z, im); im = fmaf(x.w, ci.w, im);
    }

    // warp reduce
    #pragma unroll
    for (int off = 16; off > 0; off >>= 1) {
        re += __shfl_xor_sync(0xffffffffu, re, off);
        im += __shfl_xor_sync(0xffffffffu, im, off);
    }

    __shared__ float sre[THREADS / 32];
    __shared__ float sim[THREADS / 32];
    const int warp = threadIdx.x >> 5;
    const int lane = threadIdx.x & 31;
    if (lane == 0) { sre[warp] = re; sim[warp] = im; }
    __syncthreads();

    if (threadIdx.x == 0) {
        float fr = 0.f, fi = 0.f;
        #pragma unroll
        for (int w = 0; w < THREADS / 32; ++w) { fr += sre[w]; fi += sim[w]; }
        float psd = fr * fr + fi * fi;
        out[b] = fmaf(psd, fc_w[0], fc_b[0]);
    }
}

extern "C" void kernel_launch(void* const* d_in, const int* in_sizes, int n_in,
                              void* d_out, int out_size) {
    const float* input = (const float*)d_in[0];   // (1024, 16384) f32
    const float* freqs = (const float*)d_in[1];   // (1024,) f32
    const float* fc_w  = (const float*)d_in[2];   // (1,1) f32
    const float* fc_b  = (const float*)d_in[3];   // (1,) f32
    float* out = (float*)d_out;                   // (1024, 1) f32

    build_weights_kernel<<<SEQ / THREADS, THREADS>>>(freqs);
    welch_reduce_kernel<<<BATCH, THREADS>>>((const float4*)input, fc_w, fc_b, out);
}